// round 4
// baseline (speedup 1.0000x reference)
#include <cuda_runtime.h>
#include <cstdint>
#include <math.h>

// ---------------- problem constants ----------------
static constexpr int BATCH  = 64;
static constexpr int NA     = 8192;
static constexpr int NB     = 8192;
static constexpr int TILE_N = 128;
static constexpr int TILE_K = 128;
static constexpr int KSPLIT = 2;                       // 64 x 2 = 128 CTAs
static constexpr int CHUNKS = NA / TILE_K / KSPLIT;    // 32

static constexpr int NTHREADS = 384;                   // 8 consumer + 4 producer warps

// s8 tiles, pitch 144 B (9 x 16B): ldmatrix + consumer LDS conflict-free
static constexpr int PITCH    = 144;
static constexpr int A_OFF    = 0;
static constexpr int B_OFF    = 128 * PITCH;           // 18432
static constexpr int STAGE_SZ = 2 * 128 * PITCH;       // 36864
static constexpr int CBSB_OFF = 2 * STAGE_SZ;          // 73728
static constexpr int CB_PITCH = 132;                   // floats
static constexpr int ACC_OFF  = CBSB_OFF + 2 * 64 * CB_PITCH * 4;  // 141312
static constexpr int SMEM_BYTES = ACC_OFF + 512;       // 141824

// ---------------- device scratch ----------------
__device__ int8_t g_A8[128 * NA];      // rows 0..63 = q(cos a), 64..127 = q(sin a); K-major
__device__ float  g_cb[BATCH * NB];
__device__ float  g_sb[BATCH * NB];
__device__ float  g_real[BATCH];
__device__ float  g_imag[BATCH];
__device__ unsigned int g_npairs;

// ---------------- helpers ----------------
__device__ __forceinline__ uint32_t smem_u32(const void* p) {
    uint32_t a;
    asm("{ .reg .u64 t; cvta.to.shared.u64 t, %1; cvt.u32.u64 %0, t; }" : "=r"(a) : "l"(p));
    return a;
}
__device__ __forceinline__ void cp_async16(uint32_t s, const void* g) {
    asm volatile("cp.async.cg.shared.global [%0], [%1], 16;" :: "r"(s), "l"(g) : "memory");
}
#define CP_COMMIT()  asm volatile("cp.async.commit_group;" ::: "memory")
#define CP_WAIT0()   asm volatile("cp.async.wait_group 0;" ::: "memory")

#define LDSM_X4(r, addr) \
    asm volatile("ldmatrix.sync.aligned.m8n8.x4.shared.b16 {%0,%1,%2,%3}, [%4];" \
        : "=r"((r)[0]), "=r"((r)[1]), "=r"((r)[2]), "=r"((r)[3]) : "r"(addr))

__device__ __forceinline__ void mma_s8(int* d, const uint32_t* a, uint32_t b0, uint32_t b1) {
    asm volatile(
        "mma.sync.aligned.m16n8k32.row.col.s32.s8.s8.s32 "
        "{%0,%1,%2,%3}, {%4,%5,%6,%7}, {%8,%9}, {%0,%1,%2,%3};"
        : "+r"(d[0]), "+r"(d[1]), "+r"(d[2]), "+r"(d[3])
        : "r"(a[0]), "r"(a[1]), "r"(a[2]), "r"(a[3]), "r"(b0), "r"(b1));
}

// ---------------- prep: quantize cos/sin(a) to s8; cos/sin(b) f32 ----------------
__global__ void plv_prep(const float* __restrict__ pa, const float* __restrict__ pb) {
    int idx = blockIdx.x * blockDim.x + threadIdx.x;
    if (idx < BATCH * NA) {
        float s, c;
        sincosf(pa[idx], &s, &c);
        int b = idx >> 13;
        int k = idx & (NA - 1);
        g_A8[(size_t)b * NA + k]        = (int8_t)__float2int_rn(127.0f * c);
        g_A8[(size_t)(b + 64) * NA + k] = (int8_t)__float2int_rn(127.0f * s);
        sincosf(pb[idx], &s, &c);
        g_cb[idx] = c;
        g_sb[idx] = s;
    }
    if (blockIdx.x == 0) {
        if (threadIdx.x < BATCH) { g_real[threadIdx.x] = 0.0f; g_imag[threadIdx.x] = 0.0f; }
        if (threadIdx.x == BATCH) g_npairs = 0u;
    }
}

// ---------------- main: warp-specialized fused mask-stream s8 GEMM ----------------
__global__ void __launch_bounds__(NTHREADS, 1) plv_main(const int* __restrict__ mask) {
    extern __shared__ char smem_raw[];
    const uint32_t sb = smem_u32(smem_raw);

    const int tid  = threadIdx.x;
    const int wid  = tid >> 5;
    const int lane = tid & 31;
    const int j0   = blockIdx.x * TILE_N;
    const long long kbase = (long long)blockIdx.y * (NA / KSPLIT);

    const bool is_consumer = (tid < 256);

    // ---------------- producer state ----------------
    const int ptid = tid - 256;            // 0..127 (valid for producers)
    const int kg   = ptid >> 5;            // k-group of 32 (== producer warp idx)
    const int n4   = ptid & 31;            // n block of 4
    unsigned int msum = 0;

    // producer: fill stage s with chunk c
    auto fill = [&](int chunk, int s) {
        const long long k0 = kbase + (long long)chunk * TILE_K;
        const uint32_t stage = sb + (uint32_t)s * STAGE_SZ;
        // A: s8 straight from gmem via cp.async (row ptid, 128 bytes)
        const char* asrc = (const char*)g_A8 + (size_t)ptid * NA + (size_t)k0;
        const uint32_t adst = stage + A_OFF + (uint32_t)ptid * PITCH;
#pragma unroll
        for (int g = 0; g < 8; ++g) cp_async16(adst + g * 16, asrc + g * 16);
        CP_COMMIT();
        // B: mask int32 -> s8, transposed to [n][k] (k-packed bytes)
        const int* mp = mask + (size_t)(k0 + kg * 32) * NB + (size_t)(j0 + n4 * 4);
        const uint32_t bbase = stage + B_OFF + (uint32_t)(n4 * 4) * PITCH + (uint32_t)(kg * 8) * 4;
#pragma unroll
        for (int kk = 0; kk < 8; ++kk) {
            const int* p = mp + (size_t)(kk * 4) * NB;
            const uint4 v0 = __ldcs((const uint4*)(p));
            const uint4 v1 = __ldcs((const uint4*)(p + NB));
            const uint4 v2 = __ldcs((const uint4*)(p + 2 * NB));
            const uint4 v3 = __ldcs((const uint4*)(p + 3 * NB));
            const uint32_t w0 = v0.x | (v1.x << 8) | (v2.x << 16) | (v3.x << 24);
            const uint32_t w1 = v0.y | (v1.y << 8) | (v2.y << 16) | (v3.y << 24);
            const uint32_t w2 = v0.z | (v1.z << 8) | (v2.z << 16) | (v3.z << 24);
            const uint32_t w3 = v0.w | (v1.w << 8) | (v2.w << 16) | (v3.w << 24);
            msum = __dp4a(w0, 0x01010101u, msum);
            msum = __dp4a(w1, 0x01010101u, msum);
            msum = __dp4a(w2, 0x01010101u, msum);
            msum = __dp4a(w3, 0x01010101u, msum);
            const uint32_t a = bbase + (uint32_t)kk * 4;
            asm volatile("st.shared.b32 [%0], %1;" :: "r"(a),             "r"(w0) : "memory");
            asm volatile("st.shared.b32 [%0], %1;" :: "r"(a + PITCH),     "r"(w1) : "memory");
            asm volatile("st.shared.b32 [%0], %1;" :: "r"(a + 2 * PITCH), "r"(w2) : "memory");
            asm volatile("st.shared.b32 [%0], %1;" :: "r"(a + 3 * PITCH), "r"(w3) : "memory");
        }
        CP_WAIT0();
    };

    // ---------------- consumer state ----------------
    const int wm = wid >> 1;               // 0..3: 32 m-rows each
    const int wn = wid & 1;                // 0..1: 64 n-cols each
    int acc[2][8][4];
#pragma unroll
    for (int i = 0; i < 2; ++i)
#pragma unroll
        for (int j = 0; j < 8; ++j)
#pragma unroll
            for (int r = 0; r < 4; ++r) acc[i][j][r] = 0;

    auto compute = [&](int s) {
        const uint32_t stage = sb + (uint32_t)s * STAGE_SZ;
        // ldmatrix addressing: lanes 0-15 rows 0..15, lanes 16-31 same rows +16B
        const uint32_t aAddr = stage + A_OFF + (uint32_t)(wm * 32) * PITCH
                             + (uint32_t)(lane & 15) * PITCH + (uint32_t)(lane >> 4) * 16;
        const uint32_t bAddr = stage + B_OFF
                             + (uint32_t)(wn * 64 + (lane >> 2)) * PITCH + (uint32_t)(lane & 3) * 4;
#pragma unroll
        for (int ks = 0; ks < 4; ++ks) {
            uint32_t afr[2][4];
            LDSM_X4(afr[0], aAddr + (uint32_t)ks * 32);
            LDSM_X4(afr[1], aAddr + 16u * PITCH + (uint32_t)ks * 32);
#pragma unroll
            for (int nj = 0; nj < 8; ++nj) {
                uint32_t b0, b1;
                const uint32_t ba = bAddr + (uint32_t)(nj * 8) * PITCH + (uint32_t)ks * 32;
                asm volatile("ld.shared.b32 %0, [%1];" : "=r"(b0) : "r"(ba));
                asm volatile("ld.shared.b32 %0, [%1];" : "=r"(b1) : "r"(ba + 16));
                mma_s8(acc[0][nj], afr[0], b0, b1);
                mma_s8(acc[1][nj], afr[1], b0, b1);
            }
        }
    };

    // ---------------- pipeline ----------------
    float* cbs = reinterpret_cast<float*>(smem_raw + CBSB_OFF);
    float* sbs = cbs + 64 * CB_PITCH;

    if (!is_consumer) fill(0, 0);
    __syncthreads();

    for (int c = 0; c < CHUNKS; ++c) {
        const int s = c & 1;
        if (is_consumer) {
            compute(s);
        } else {
            if (c + 1 < CHUNKS) fill(c + 1, s ^ 1);
            if (c == 0) {
                // prefetch epilogue cb/sb tiles (64KB) while consumers crunch
#pragma unroll
                for (int it = 0; it < 16; ++it) {
                    const int idx = ptid + it * 128;   // 0..2047 float4 tasks
                    const int b  = idx >> 5;
                    const int nf = idx & 31;
                    *reinterpret_cast<float4*>(&cbs[b * CB_PITCH + nf * 4]) =
                        *reinterpret_cast<const float4*>(&g_cb[(size_t)b * NB + j0 + nf * 4]);
                    *reinterpret_cast<float4*>(&sbs[b * CB_PITCH + nf * 4]) =
                        *reinterpret_cast<const float4*>(&g_sb[(size_t)b * NB + j0 + nf * 4]);
                }
            }
        }
        __syncthreads();
    }

    // ---------------- n_pairs reduce (producers only) ----------------
    if (!is_consumer) {
#pragma unroll
        for (int o = 16; o; o >>= 1) msum += __shfl_down_sync(0xFFFFFFFFu, msum, o);
        if (lane == 0) atomicAdd(&g_npairs, msum);
    }

    // ---------------- epilogue (consumers) ----------------
    float* real_s = reinterpret_cast<float*>(smem_raw + ACC_OFF);
    float* imag_s = real_s + 64;
    if (tid < 64) { real_s[tid] = 0.0f; imag_s[tid] = 0.0f; }
    __syncthreads();

    if (is_consumer) {
        const bool isCos = (wm < 2);
        const int  tq = lane >> 2;
        const int  tc = (lane & 3) * 2;
        const float inv127 = 1.0f / 127.0f;
#pragma unroll
        for (int mi = 0; mi < 2; ++mi) {
#pragma unroll
            for (int h = 0; h < 2; ++h) {
                const int m = wm * 32 + mi * 16 + h * 8 + tq;
                const int b = m & 63;
                float racc = 0.0f, iacc = 0.0f;
#pragma unroll
                for (int nj = 0; nj < 8; ++nj) {
                    const int n = wn * 64 + nj * 8 + tc;
                    const float dlo = __int2float_rn(acc[mi][nj][h * 2 + 0]);
                    const float dhi = __int2float_rn(acc[mi][nj][h * 2 + 1]);
                    const float2 cv = *reinterpret_cast<const float2*>(&cbs[b * CB_PITCH + n]);
                    const float2 sv = *reinterpret_cast<const float2*>(&sbs[b * CB_PITCH + n]);
                    if (isCos) {
                        racc = fmaf(dlo, cv.x, fmaf(dhi, cv.y, racc));
                        iacc = fmaf(-dlo, sv.x, fmaf(-dhi, sv.y, iacc));
                    } else {
                        racc = fmaf(dlo, sv.x, fmaf(dhi, sv.y, racc));
                        iacc = fmaf(dlo, cv.x, fmaf(dhi, cv.y, iacc));
                    }
                }
                atomicAdd(&real_s[b], racc * inv127);
                atomicAdd(&imag_s[b], iacc * inv127);
            }
        }
    }
    __syncthreads();
    if (tid < 64) {
        atomicAdd(&g_real[tid], real_s[tid]);
        atomicAdd(&g_imag[tid], imag_s[tid]);
    }
}

// ---------------- final ----------------
__global__ void plv_final(float* __restrict__ out) {
    const int b = threadIdx.x;
    if (b < BATCH) {
        const float np = fmaxf((float)g_npairs, 1.0f);
        const float r = g_real[b], i = g_imag[b];
        out[b] = sqrtf(r * r + i * i) / np;
    }
}

// ---------------- launch ----------------
extern "C" void kernel_launch(void* const* d_in, const int* in_sizes, int n_in,
                              void* d_out, int out_size) {
    (void)in_sizes; (void)n_in; (void)out_size;
    const float* pa = (const float*)d_in[0];
    const float* pb = (const float*)d_in[1];
    const int* mask = (const int*)d_in[2];
    float* out      = (float*)d_out;

    cudaFuncSetAttribute(plv_main, cudaFuncAttributeMaxDynamicSharedMemorySize, SMEM_BYTES);

    plv_prep<<<(BATCH * NA + 255) / 256, 256>>>(pa, pb);
    plv_main<<<dim3(NB / TILE_N, KSPLIT), 384, SMEM_BYTES>>>(mask);
    plv_final<<<1, 64>>>(out);
}

// round 5
// speedup vs baseline: 1.2902x; 1.2902x over previous
#include <cuda_runtime.h>
#include <cstdint>
#include <math.h>

// ---------------- problem constants ----------------
static constexpr int BATCH  = 64;
static constexpr int NA     = 8192;
static constexpr int NB     = 8192;
static constexpr int TILE_N = 128;
static constexpr int TILE_K = 128;
static constexpr int KSPLIT = 2;                       // 64 x 2 = 128 CTAs
static constexpr int CHUNKS = NA / TILE_K / KSPLIT;    // 32

static constexpr int NTHREADS = 256;

// smem layout
static constexpr int PITCH    = 144;                   // s8 tile pitch (9 x 16B)
static constexpr int RAW_PITCH = 512;                  // raw mask row: 128 int32
static constexpr int RAW_SZ   = 128 * RAW_PITCH;       // 65536
static constexpr int A_OFF    = 0;                     // within stage
static constexpr int B_OFF    = 128 * PITCH;           // 18432
static constexpr int STAGE_SZ = 2 * 128 * PITCH;       // 36864
static constexpr int STAGE0   = 2 * RAW_SZ;            // 131072
static constexpr int ACC_OFF  = STAGE0 + 2 * STAGE_SZ; // 204800
static constexpr int SMEM_BYTES = ACC_OFF + 512;       // 205312

// ---------------- device scratch ----------------
__device__ int8_t g_A8[128 * NA];      // rows 0..63 = q(cos a), 64..127 = q(sin a); K-major
__device__ float  g_cb[BATCH * NB];
__device__ float  g_sb[BATCH * NB];
__device__ float  g_real[BATCH];
__device__ float  g_imag[BATCH];
__device__ unsigned int g_npairs;

// ---------------- helpers ----------------
__device__ __forceinline__ uint32_t smem_u32(const void* p) {
    uint32_t a;
    asm("{ .reg .u64 t; cvta.to.shared.u64 t, %1; cvt.u32.u64 %0, t; }" : "=r"(a) : "l"(p));
    return a;
}
__device__ __forceinline__ void cp_async16(uint32_t s, const void* g) {
    asm volatile("cp.async.cg.shared.global [%0], [%1], 16;" :: "r"(s), "l"(g) : "memory");
}
#define CP_COMMIT()  asm volatile("cp.async.commit_group;" ::: "memory")
#define CP_WAIT0()   asm volatile("cp.async.wait_group 0;" ::: "memory")

#define LDSM_X4(r, addr) \
    asm volatile("ldmatrix.sync.aligned.m8n8.x4.shared.b16 {%0,%1,%2,%3}, [%4];" \
        : "=r"((r)[0]), "=r"((r)[1]), "=r"((r)[2]), "=r"((r)[3]) : "r"(addr))

__device__ __forceinline__ void mma_s8(int* d, const uint32_t* a, uint32_t b0, uint32_t b1) {
    asm volatile(
        "mma.sync.aligned.m16n8k32.row.col.s32.s8.s8.s32 "
        "{%0,%1,%2,%3}, {%4,%5,%6,%7}, {%8,%9}, {%0,%1,%2,%3};"
        : "+r"(d[0]), "+r"(d[1]), "+r"(d[2]), "+r"(d[3])
        : "r"(a[0]), "r"(a[1]), "r"(a[2]), "r"(a[3]), "r"(b0), "r"(b1));
}

// ---------------- prep: quantize cos/sin(a) to s8; cos/sin(b) f32 ----------------
__global__ void plv_prep(const float* __restrict__ pa, const float* __restrict__ pb) {
    int idx = blockIdx.x * blockDim.x + threadIdx.x;
    if (idx < BATCH * NA) {
        float s, c;
        sincosf(pa[idx], &s, &c);
        int b = idx >> 13;
        int k = idx & (NA - 1);
        g_A8[(size_t)b * NA + k]        = (int8_t)__float2int_rn(127.0f * c);
        g_A8[(size_t)(b + 64) * NA + k] = (int8_t)__float2int_rn(127.0f * s);
        sincosf(pb[idx], &s, &c);
        g_cb[idx] = c;
        g_sb[idx] = s;
    }
    if (blockIdx.x == 0) {
        if (threadIdx.x < BATCH) { g_real[threadIdx.x] = 0.0f; g_imag[threadIdx.x] = 0.0f; }
        if (threadIdx.x == BATCH) g_npairs = 0u;
    }
}

// ---------------- main: fused mask-stream s8 GEMM, cp.async raw staging ----------------
__global__ void __launch_bounds__(NTHREADS, 1) plv_main(const int* __restrict__ mask) {
    extern __shared__ char smem_raw[];
    const uint32_t sb = smem_u32(smem_raw);

    const int tid  = threadIdx.x;
    const int wid  = tid >> 5;
    const int lane = tid & 31;
    const int j0   = blockIdx.x * TILE_N;
    const long long kbase = (long long)blockIdx.y * (NA / KSPLIT);

    unsigned int msum = 0;

    // ---- issue async loads for chunk c into buffers [s] (raw mask + A s8) ----
    auto issue = [&](int chunk, int s) {
        const long long k0 = kbase + (long long)chunk * TILE_K;
        // raw mask: 128 rows x 512B; 4096 16B tasks over 256 threads
        const uint32_t rawdst = sb + (uint32_t)s * RAW_SZ;
        const int* src = mask + (size_t)k0 * NB + j0;
#pragma unroll
        for (int it = 0; it < 16; ++it) {
            const int idx = tid + it * 256;
            const int k  = idx >> 5;
            const int nb = idx & 31;
            cp_async16(rawdst + (uint32_t)k * RAW_PITCH + (uint32_t)nb * 16,
                       src + (size_t)k * NB + nb * 4);
        }
        // A tile: 128 rows x 128B; 1024 16B tasks
        const uint32_t adst = sb + STAGE0 + (uint32_t)s * STAGE_SZ + A_OFF;
#pragma unroll
        for (int it = 0; it < 4; ++it) {
            const int idx = tid + it * 256;
            const int m  = idx >> 3;
            const int g  = idx & 7;
            cp_async16(adst + (uint32_t)m * PITCH + (uint32_t)g * 16,
                       (const char*)g_A8 + (size_t)m * NA + (size_t)k0 + (size_t)g * 16);
        }
        CP_COMMIT();
    };

    // ---- convert raw[s] (int32 [k][n]) -> B stage[s] (s8 [n][k-packed]) ----
    const int n4 = tid & 31;          // n-block of 4
    const int kq = tid >> 5;          // 0..7, 16 k each
    auto convert = [&](int s) {
        const uint32_t rawb = sb + (uint32_t)s * RAW_SZ;
        const uint32_t bdst = sb + STAGE0 + (uint32_t)s * STAGE_SZ + B_OFF;
#pragma unroll
        for (int q = 0; q < 4; ++q) {
            const int k = kq * 16 + q * 4;
            uint4 v0, v1, v2, v3;
            const uint32_t ra = rawb + (uint32_t)k * RAW_PITCH + (uint32_t)n4 * 16;
            asm volatile("ld.shared.v4.b32 {%0,%1,%2,%3}, [%4];"
                : "=r"(v0.x), "=r"(v0.y), "=r"(v0.z), "=r"(v0.w) : "r"(ra));
            asm volatile("ld.shared.v4.b32 {%0,%1,%2,%3}, [%4];"
                : "=r"(v1.x), "=r"(v1.y), "=r"(v1.z), "=r"(v1.w) : "r"(ra + RAW_PITCH));
            asm volatile("ld.shared.v4.b32 {%0,%1,%2,%3}, [%4];"
                : "=r"(v2.x), "=r"(v2.y), "=r"(v2.z), "=r"(v2.w) : "r"(ra + 2 * RAW_PITCH));
            asm volatile("ld.shared.v4.b32 {%0,%1,%2,%3}, [%4];"
                : "=r"(v3.x), "=r"(v3.y), "=r"(v3.z), "=r"(v3.w) : "r"(ra + 3 * RAW_PITCH));
            const uint32_t w0 = v0.x | (v1.x << 8) | (v2.x << 16) | (v3.x << 24);
            const uint32_t w1 = v0.y | (v1.y << 8) | (v2.y << 16) | (v3.y << 24);
            const uint32_t w2 = v0.z | (v1.z << 8) | (v2.z << 16) | (v3.z << 24);
            const uint32_t w3 = v0.w | (v1.w << 8) | (v2.w << 16) | (v3.w << 24);
            msum = __dp4a(w0, 0x01010101u, msum);
            msum = __dp4a(w1, 0x01010101u, msum);
            msum = __dp4a(w2, 0x01010101u, msum);
            msum = __dp4a(w3, 0x01010101u, msum);
            const uint32_t ba = bdst + (uint32_t)(n4 * 4) * PITCH + (uint32_t)(kq * 16 + q * 4);
            asm volatile("st.shared.b32 [%0], %1;" :: "r"(ba),             "r"(w0) : "memory");
            asm volatile("st.shared.b32 [%0], %1;" :: "r"(ba + PITCH),     "r"(w1) : "memory");
            asm volatile("st.shared.b32 [%0], %1;" :: "r"(ba + 2 * PITCH), "r"(w2) : "memory");
            asm volatile("st.shared.b32 [%0], %1;" :: "r"(ba + 3 * PITCH), "r"(w3) : "memory");
        }
    };

    // ---- consumer state ----
    const int wm = wid >> 1;               // 0..3: 32 m-rows each
    const int wn = wid & 1;                // 0..1: 64 n-cols each
    int acc[2][8][4];
#pragma unroll
    for (int i = 0; i < 2; ++i)
#pragma unroll
        for (int j = 0; j < 8; ++j)
#pragma unroll
            for (int r = 0; r < 4; ++r) acc[i][j][r] = 0;

    auto compute = [&](int s) {
        const uint32_t stage = sb + STAGE0 + (uint32_t)s * STAGE_SZ;
        const uint32_t aAddr = stage + A_OFF + (uint32_t)(wm * 32) * PITCH
                             + (uint32_t)(lane & 15) * PITCH + (uint32_t)(lane >> 4) * 16;
        const uint32_t bAddr = stage + B_OFF
                             + (uint32_t)(wn * 64 + (lane >> 2)) * PITCH + (uint32_t)(lane & 3) * 4;
#pragma unroll
        for (int ks = 0; ks < 4; ++ks) {
            uint32_t afr[2][4];
            LDSM_X4(afr[0], aAddr + (uint32_t)ks * 32);
            LDSM_X4(afr[1], aAddr + 16u * PITCH + (uint32_t)ks * 32);
#pragma unroll
            for (int nj = 0; nj < 8; ++nj) {
                uint32_t b0, b1;
                const uint32_t ba = bAddr + (uint32_t)(nj * 8) * PITCH + (uint32_t)ks * 32;
                asm volatile("ld.shared.b32 %0, [%1];" : "=r"(b0) : "r"(ba));
                asm volatile("ld.shared.b32 %0, [%1];" : "=r"(b1) : "r"(ba + 16));
                mma_s8(acc[0][nj], afr[0], b0, b1);
                mma_s8(acc[1][nj], afr[1], b0, b1);
            }
        }
    };

    // ---------------- pipeline ----------------
    issue(0, 0);
    CP_WAIT0();
    __syncthreads();

    for (int c = 0; c < CHUNKS; ++c) {
        const int s = c & 1;
        if (c + 1 < CHUNKS) issue(c + 1, s ^ 1);
        convert(s);
        __syncthreads();
        compute(s);
        CP_WAIT0();
        __syncthreads();
    }

    // ---- n_pairs reduce ----
#pragma unroll
    for (int o = 16; o; o >>= 1) msum += __shfl_down_sync(0xFFFFFFFFu, msum, o);
    if (lane == 0) atomicAdd(&g_npairs, msum);

    // ---- epilogue: fuse cb/sb (direct gmem) + reduce to smem then global ----
    float* real_s = reinterpret_cast<float*>(smem_raw + ACC_OFF);
    float* imag_s = real_s + 64;
    if (tid < 64) { real_s[tid] = 0.0f; imag_s[tid] = 0.0f; }
    __syncthreads();

    {
        const bool isCos = (wm < 2);
        const int  tq = lane >> 2;
        const int  tc = (lane & 3) * 2;
        const float inv127 = 1.0f / 127.0f;
#pragma unroll
        for (int mi = 0; mi < 2; ++mi) {
#pragma unroll
            for (int h = 0; h < 2; ++h) {
                const int m = wm * 32 + mi * 16 + h * 8 + tq;
                const int b = m & 63;
                float racc = 0.0f, iacc = 0.0f;
#pragma unroll
                for (int nj = 0; nj < 8; ++nj) {
                    const int n = wn * 64 + nj * 8 + tc;
                    const float dlo = __int2float_rn(acc[mi][nj][h * 2 + 0]);
                    const float dhi = __int2float_rn(acc[mi][nj][h * 2 + 1]);
                    const float2 cv = __ldg((const float2*)&g_cb[(size_t)b * NB + j0 + n]);
                    const float2 sv = __ldg((const float2*)&g_sb[(size_t)b * NB + j0 + n]);
                    if (isCos) {
                        racc = fmaf(dlo, cv.x, fmaf(dhi, cv.y, racc));
                        iacc = fmaf(-dlo, sv.x, fmaf(-dhi, sv.y, iacc));
                    } else {
                        racc = fmaf(dlo, sv.x, fmaf(dhi, sv.y, racc));
                        iacc = fmaf(dlo, cv.x, fmaf(dhi, cv.y, iacc));
                    }
                }
                atomicAdd(&real_s[b], racc * inv127);
                atomicAdd(&imag_s[b], iacc * inv127);
            }
        }
    }
    __syncthreads();
    if (tid < 64) {
        atomicAdd(&g_real[tid], real_s[tid]);
        atomicAdd(&g_imag[tid], imag_s[tid]);
    }
}

// ---------------- final ----------------
__global__ void plv_final(float* __restrict__ out) {
    const int b = threadIdx.x;
    if (b < BATCH) {
        const float np = fmaxf((float)g_npairs, 1.0f);
        const float r = g_real[b], i = g_imag[b];
        out[b] = sqrtf(r * r + i * i) / np;
    }
}

// ---------------- launch ----------------
extern "C" void kernel_launch(void* const* d_in, const int* in_sizes, int n_in,
                              void* d_out, int out_size) {
    (void)in_sizes; (void)n_in; (void)out_size;
    const float* pa = (const float*)d_in[0];
    const float* pb = (const float*)d_in[1];
    const int* mask = (const int*)d_in[2];
    float* out      = (float*)d_out;

    cudaFuncSetAttribute(plv_main, cudaFuncAttributeMaxDynamicSharedMemorySize, SMEM_BYTES);

    plv_prep<<<(BATCH * NA + 255) / 256, 256>>>(pa, pb);
    plv_main<<<dim3(NB / TILE_N, KSPLIT), NTHREADS, SMEM_BYTES>>>(mask);
    plv_final<<<1, 64>>>(out);
}

// round 7
// speedup vs baseline: 1.3473x; 1.0443x over previous
#include <cuda_runtime.h>
#include <cstdint>
#include <math.h>

// ---------------- problem constants ----------------
static constexpr int BATCH  = 64;
static constexpr int NA     = 8192;     // i dimension (mask rows)
static constexpr int NB     = 8192;     // j dimension (mask cols)
static constexpr int TILE_K = 128;      // j per chunk
static constexpr int JSPLIT = 2;        // 64 i-tiles x 2 j-strips = 128 CTAs
static constexpr int CHUNKS = NB / TILE_K / JSPLIT;   // 32
static constexpr int NTHREADS = 256;

// smem: B stages (s8 [r=128][k-packed 128B], pitch 144) overlapped later by ca/sa f32
static constexpr int PITCH    = 144;
static constexpr int STAGE_SZ = 128 * PITCH;           // 18432
static constexpr int CA_PITCH = 132;                   // floats
static constexpr int ACC_OFF  = 2 * 64 * CA_PITCH * 4; // 67584 (> 2*STAGE_SZ)
static constexpr int SMEM_BYTES = ACC_OFF + 512;       // 68096

// ---------------- device scratch ----------------
__device__ int8_t g_B8[128 * NB];      // rows 0..63 = q127(cos b), 64..127 = q127(sin b); j-major
__device__ float  g_caf[BATCH * NA];   // cos(a), b-major
__device__ float  g_saf[BATCH * NA];   // sin(a)
__device__ float  g_real[BATCH];
__device__ float  g_imag[BATCH];
__device__ unsigned int g_npairs;

// ---------------- helpers ----------------
__device__ __forceinline__ uint32_t smem_u32(const void* p) {
    uint32_t a;
    asm("{ .reg .u64 t; cvta.to.shared.u64 t, %1; cvt.u32.u64 %0, t; }" : "=r"(a) : "l"(p));
    return a;
}
__device__ __forceinline__ void cp_async16(uint32_t s, const void* g) {
    asm volatile("cp.async.cg.shared.global [%0], [%1], 16;" :: "r"(s), "l"(g) : "memory");
}
#define CP_COMMIT()  asm volatile("cp.async.commit_group;" ::: "memory")
#define CP_WAIT0()   asm volatile("cp.async.wait_group 0;" ::: "memory")

__device__ __forceinline__ void mma_s8(int* d, const uint32_t* a, uint32_t b0, uint32_t b1) {
    asm volatile(
        "mma.sync.aligned.m16n8k32.row.col.s32.s8.s8.s32 "
        "{%0,%1,%2,%3}, {%4,%5,%6,%7}, {%8,%9}, {%0,%1,%2,%3};"
        : "+r"(d[0]), "+r"(d[1]), "+r"(d[2]), "+r"(d[3])
        : "r"(a[0]), "r"(a[1]), "r"(a[2]), "r"(a[3]), "r"(b0), "r"(b1));
}
__device__ __forceinline__ uint32_t pack01(const uint4 v) {
    // int32 {0,1} x4 -> 4 s8 bytes (exact)
    return v.x | (v.y << 8) | (v.z << 16) | (v.w << 24);
}

// ---------------- prep: f32 cos/sin(a); s8 q127 cos/sin(b) ----------------
__global__ void plv_prep(const float* __restrict__ pa, const float* __restrict__ pb) {
    int idx = blockIdx.x * blockDim.x + threadIdx.x;
    if (idx < BATCH * NA) {
        float s, c;
        sincosf(pa[idx], &s, &c);
        g_caf[idx] = c;
        g_saf[idx] = s;
        sincosf(pb[idx], &s, &c);
        int b = idx >> 13;
        int j = idx & (NB - 1);
        g_B8[(size_t)b * NB + j]        = (int8_t)__float2int_rn(127.0f * c);
        g_B8[(size_t)(b + 64) * NB + j] = (int8_t)__float2int_rn(127.0f * s);
    }
    if (blockIdx.x == 0) {
        if (threadIdx.x < BATCH) { g_real[threadIdx.x] = 0.0f; g_imag[threadIdx.x] = 0.0f; }
        if (threadIdx.x == BATCH) g_npairs = 0u;
    }
}

// ---------------- main: X = M @ [cb;sb]^T fused with f32 ca/sa epilogue ----------------
__global__ void __launch_bounds__(NTHREADS, 1) plv_main(const int* __restrict__ mask) {
    extern __shared__ char smem_raw[];
    const uint32_t sb = smem_u32(smem_raw);

    const int tid  = threadIdx.x;
    const int wid  = tid >> 5;          // 8 warps: 16 i-rows each
    const int lane = tid & 31;
    const int i0   = blockIdx.x * 128;
    const int jb   = blockIdx.y * (NB / JSPLIT);   // j strip base

    // ---- B stage issue: g_B8[r][j-chunk] -> stage s (s8, pitch 144) ----
    auto issueB = [&](int chunk, int s) {
        const int j0 = jb + chunk * TILE_K;
        const uint32_t dst = sb + (uint32_t)s * STAGE_SZ;
#pragma unroll
        for (int it = 0; it < 4; ++it) {
            const int idx = tid + it * 256;
            const int r = idx >> 3;
            const int g = idx & 7;
            cp_async16(dst + (uint32_t)r * PITCH + (uint32_t)g * 16,
                       (const char*)g_B8 + (size_t)r * NB + (size_t)j0 + (size_t)g * 16);
        }
        CP_COMMIT();
    };

    // ---- A fragment loads: straight from mask gmem (no smem, no transpose) ----
    const int   arow = i0 + wid * 16 + (lane >> 2);
    const int* rp0 = mask + (size_t)arow * NB;
    const int* rp1 = rp0 + (size_t)8 * NB;
    const int   jlane = (lane & 3) * 4;

    uint4 rawv[2][4];
    auto load_frags = [&](int g, uint4* r) {
        const int j = jb + (g >> 2) * TILE_K + (g & 3) * 32 + jlane;
        r[0] = __ldcs((const uint4*)(rp0 + j));
        r[1] = __ldcs((const uint4*)(rp1 + j));
        r[2] = __ldcs((const uint4*)(rp0 + j + 16));
        r[3] = __ldcs((const uint4*)(rp1 + j + 16));
    };

    int acc[16][4];
#pragma unroll
    for (int nj = 0; nj < 16; ++nj)
#pragma unroll
        for (int r = 0; r < 4; ++r) acc[nj][r] = 0;

    unsigned int msum = 0;
    const uint32_t bOff = (uint32_t)(lane >> 2) * PITCH + (uint32_t)(lane & 3) * 4;

    // ---- prologue ----
    issueB(0, 0);
    load_frags(0, rawv[0]);
    load_frags(1, rawv[1]);
    CP_WAIT0();
    __syncthreads();

    const int TOTAL_G = CHUNKS * 4;
    for (int c = 0; c < CHUNKS; ++c) {
        if (c + 1 < CHUNKS) issueB(c + 1, (c + 1) & 1);
        const uint32_t stg = sb + (uint32_t)(c & 1) * STAGE_SZ;
#pragma unroll
        for (int ks = 0; ks < 4; ++ks) {
            const int g = c * 4 + ks;
            uint32_t af[4];
            af[0] = pack01(rawv[g & 1][0]);
            af[1] = pack01(rawv[g & 1][1]);
            af[2] = pack01(rawv[g & 1][2]);
            af[3] = pack01(rawv[g & 1][3]);
            msum = __dp4a(af[0], 0x01010101u, msum);
            msum = __dp4a(af[1], 0x01010101u, msum);
            msum = __dp4a(af[2], 0x01010101u, msum);
            msum = __dp4a(af[3], 0x01010101u, msum);
            if (g + 2 < TOTAL_G) load_frags(g + 2, rawv[g & 1]);
            const uint32_t bk = stg + bOff + (uint32_t)ks * 32;
#pragma unroll
            for (int nj = 0; nj < 16; ++nj) {
                uint32_t b0, b1;
                const uint32_t ba = bk + (uint32_t)(nj * 8) * PITCH;
                asm volatile("ld.shared.b32 %0, [%1];" : "=r"(b0) : "r"(ba));
                asm volatile("ld.shared.b32 %0, [%1];" : "=r"(b1) : "r"(ba + 16));
                mma_s8(acc[nj], af, b0, b1);
            }
        }
        CP_WAIT0();
        __syncthreads();
    }

    // ---- n_pairs reduce ----
#pragma unroll
    for (int o = 16; o; o >>= 1) msum += __shfl_down_sync(0xFFFFFFFFu, msum, o);
    if (lane == 0) atomicAdd(&g_npairs, msum);

    // ---- stage ca/sa [64 b][128 i-tile] f32 into smem (reuses B stage space) ----
    float* cas = reinterpret_cast<float*>(smem_raw);
    float* sas = cas + 64 * CA_PITCH;
    float* real_s = reinterpret_cast<float*>(smem_raw + ACC_OFF);
    float* imag_s = real_s + 64;
    if (tid < 64) { real_s[tid] = 0.0f; imag_s[tid] = 0.0f; }
#pragma unroll
    for (int it = 0; it < 8; ++it) {
        const int idx = tid + it * 256;   // 0..2047 float4 tasks
        const int r = idx >> 5;
        const int q = idx & 31;
        *reinterpret_cast<float4*>(&cas[r * CA_PITCH + q * 4]) =
            *reinterpret_cast<const float4*>(&g_caf[(size_t)r * NA + i0 + q * 4]);
        *reinterpret_cast<float4*>(&sas[r * CA_PITCH + q * 4]) =
            *reinterpret_cast<const float4*>(&g_saf[(size_t)r * NA + i0 + q * 4]);
    }
    __syncthreads();

    // ---- epilogue: real_b += ca*Xc + sa*Xs ; imag_b += sa*Xc - ca*Xs ----
    {
        const float inv127 = 1.0f / 127.0f;
        const int tc  = (lane & 3) * 2;
        const int il0 = wid * 16 + (lane >> 2);
#pragma unroll
        for (int nj = 0; nj < 8; ++nj) {
#pragma unroll
            for (int h2 = 0; h2 < 2; ++h2) {
                const int b = nj * 8 + tc + h2;
                float rsum = 0.0f, isum = 0.0f;
#pragma unroll
                for (int hr = 0; hr < 2; ++hr) {
                    const int il = il0 + hr * 8;
                    const float Xc = __int2float_rn(acc[nj][hr * 2 + h2]);
                    const float Xs = __int2float_rn(acc[nj + 8][hr * 2 + h2]);
                    const float ca = cas[b * CA_PITCH + il];
                    const float sa = sas[b * CA_PITCH + il];
                    rsum = fmaf(ca, Xc, fmaf(sa, Xs, rsum));
                    isum = fmaf(sa, Xc, fmaf(-ca, Xs, isum));
                }
                atomicAdd(&real_s[b], rsum * inv127);
                atomicAdd(&imag_s[b], isum * inv127);
            }
        }
    }
    __syncthreads();
    if (tid < 64) {
        atomicAdd(&g_real[tid], real_s[tid]);
        atomicAdd(&g_imag[tid], imag_s[tid]);
    }
}

// ---------------- final ----------------
__global__ void plv_final(float* __restrict__ out) {
    const int b = threadIdx.x;
    if (b < BATCH) {
        const float np = fmaxf((float)g_npairs, 1.0f);
        const float r = g_real[b], i = g_imag[b];
        out[b] = sqrtf(r * r + i * i) / np;
    }
}

// ---------------- launch ----------------
extern "C" void kernel_launch(void* const* d_in, const int* in_sizes, int n_in,
                              void* d_out, int out_size) {
    (void)in_sizes; (void)n_in; (void)out_size;
    const float* pa = (const float*)d_in[0];
    const float* pb = (const float*)d_in[1];
    const int* mask = (const int*)d_in[2];
    float* out      = (float*)d_out;

    cudaFuncSetAttribute(plv_main, cudaFuncAttributeMaxDynamicSharedMemorySize, SMEM_BYTES);

    plv_prep<<<(BATCH * NA + 255) / 256, 256>>>(pa, pb);
    plv_main<<<dim3(NA / 128, JSPLIT), NTHREADS, SMEM_BYTES>>>(mask);
    plv_final<<<1, 64>>>(out);
}

// round 8
// speedup vs baseline: 1.3790x; 1.0235x over previous
#include <cuda_runtime.h>
#include <cstdint>
#include <math.h>

// ---------------- problem constants ----------------
static constexpr int BATCH  = 64;
static constexpr int NA     = 8192;     // i dimension (mask rows)
static constexpr int NB     = 8192;     // j dimension (mask cols)
static constexpr int TILE_K = 128;      // j per chunk
static constexpr int JSPLIT = 2;        // 64 i-tiles x 2 j-strips = 128 CTAs
static constexpr int CHUNKS = NB / TILE_K / JSPLIT;   // 32
static constexpr int NTHREADS = 256;

// smem: B ring (3 stages, s8 [r=128][k-packed 128B], pitch 144), then ca/sa f32
static constexpr int PITCH    = 144;
static constexpr int STAGE_SZ = 128 * PITCH;           // 18432 (x3 = 55296)
static constexpr int CA_PITCH = 132;                   // floats
static constexpr int ACC_OFF  = 2 * 64 * CA_PITCH * 4; // 67584 (> 3*STAGE_SZ)
static constexpr int SMEM_BYTES = ACC_OFF + 512;       // 68096

// ---------------- device scratch ----------------
__device__ int8_t g_B8[128 * NB];      // rows 0..63 = q127(cos b), 64..127 = q127(sin b); j-major
__device__ float  g_caf[BATCH * NA];   // cos(a), b-major
__device__ float  g_saf[BATCH * NA];   // sin(a)
__device__ float  g_real[BATCH];
__device__ float  g_imag[BATCH];
__device__ unsigned int g_npairs;

// ---------------- helpers ----------------
__device__ __forceinline__ uint32_t smem_u32(const void* p) {
    uint32_t a;
    asm("{ .reg .u64 t; cvta.to.shared.u64 t, %1; cvt.u32.u64 %0, t; }" : "=r"(a) : "l"(p));
    return a;
}
__device__ __forceinline__ void cp_async16(uint32_t s, const void* g) {
    asm volatile("cp.async.cg.shared.global [%0], [%1], 16;" :: "r"(s), "l"(g) : "memory");
}
#define CP_COMMIT()  asm volatile("cp.async.commit_group;" ::: "memory")
#define CP_WAIT1()   asm volatile("cp.async.wait_group 1;" ::: "memory")

__device__ __forceinline__ void prefetchL2(const void* g) {
    asm volatile("prefetch.global.L2 [%0];" :: "l"(g));
}

__device__ __forceinline__ void mma_s8(int* d, const uint32_t* a, uint32_t b0, uint32_t b1) {
    asm volatile(
        "mma.sync.aligned.m16n8k32.row.col.s32.s8.s8.s32 "
        "{%0,%1,%2,%3}, {%4,%5,%6,%7}, {%8,%9}, {%0,%1,%2,%3};"
        : "+r"(d[0]), "+r"(d[1]), "+r"(d[2]), "+r"(d[3])
        : "r"(a[0]), "r"(a[1]), "r"(a[2]), "r"(a[3]), "r"(b0), "r"(b1));
}
__device__ __forceinline__ uint32_t pack01(const uint4 v) {
    return v.x | (v.y << 8) | (v.z << 16) | (v.w << 24);
}

// ---------------- prep: f32 cos/sin(a); s8 q127 cos/sin(b) ----------------
__global__ void plv_prep(const float* __restrict__ pa, const float* __restrict__ pb) {
    int idx = blockIdx.x * blockDim.x + threadIdx.x;
    if (idx < BATCH * NA) {
        float s, c;
        sincosf(pa[idx], &s, &c);
        g_caf[idx] = c;
        g_saf[idx] = s;
        sincosf(pb[idx], &s, &c);
        int b = idx >> 13;
        int j = idx & (NB - 1);
        g_B8[(size_t)b * NB + j]        = (int8_t)__float2int_rn(127.0f * c);
        g_B8[(size_t)(b + 64) * NB + j] = (int8_t)__float2int_rn(127.0f * s);
    }
    if (blockIdx.x == 0) {
        if (threadIdx.x < BATCH) { g_real[threadIdx.x] = 0.0f; g_imag[threadIdx.x] = 0.0f; }
        if (threadIdx.x == BATCH) g_npairs = 0u;
    }
}

// ---------------- main: X = M @ [cb;sb]^T fused with f32 ca/sa epilogue ----------------
__global__ void __launch_bounds__(NTHREADS, 1) plv_main(const int* __restrict__ mask) {
    extern __shared__ char smem_raw[];
    const uint32_t sb = smem_u32(smem_raw);

    const int tid  = threadIdx.x;
    const int wid  = tid >> 5;          // 8 warps: 16 i-rows each
    const int lane = tid & 31;
    const int i0   = blockIdx.x * 128;
    const int jb   = blockIdx.y * (NB / JSPLIT);   // j strip base

    // ---- B ring issue: g_B8[r][j-chunk] -> stage (chunk % 3) ----
    auto issueB = [&](int chunk) {
        const int j0 = jb + chunk * TILE_K;
        const uint32_t dst = sb + (uint32_t)(chunk % 3) * STAGE_SZ;
#pragma unroll
        for (int it = 0; it < 4; ++it) {
            const int idx = tid + it * 256;
            const int r = idx >> 3;
            const int g = idx & 7;
            cp_async16(dst + (uint32_t)r * PITCH + (uint32_t)g * 16,
                       (const char*)g_B8 + (size_t)r * NB + (size_t)j0 + (size_t)g * 16);
        }
        CP_COMMIT();
    };

    // ---- A fragment loads: straight from mask gmem (no smem, no transpose) ----
    const int   arow = i0 + wid * 16 + (lane >> 2);
    const int* rp0 = mask + (size_t)arow * NB;
    const int* rp1 = rp0 + (size_t)8 * NB;
    const int   jlane = (lane & 3) * 4;

    uint4 rawv[2][4];
    auto load_frags = [&](int g, uint4* r) {
        const int j = jb + (g >> 2) * TILE_K + (g & 3) * 32 + jlane;
        r[0] = __ldcs((const uint4*)(rp0 + j));
        r[1] = __ldcs((const uint4*)(rp1 + j));
        r[2] = __ldcs((const uint4*)(rp0 + j + 16));
        r[3] = __ldcs((const uint4*)(rp1 + j + 16));
    };

    // ---- L2 prefetch of a whole chunk's mask rows for this thread's rows ----
    // lanes with (lane&3)==0 prefetch; each 128B line covers the +0 and +16 loads.
    auto prefetch_chunk = [&](int chunk) {
        if ((lane & 3) == 0) {
            const int jc = jb + chunk * TILE_K;
#pragma unroll
            for (int g = 0; g < 4; ++g) {
                const int j = jc + g * 32;
                prefetchL2(rp0 + j);
                prefetchL2(rp1 + j);
            }
        }
    };

    int acc[16][4];
#pragma unroll
    for (int nj = 0; nj < 16; ++nj)
#pragma unroll
        for (int r = 0; r < 4; ++r) acc[nj][r] = 0;

    unsigned int msum = 0;
    const uint32_t bOff = (uint32_t)(lane >> 2) * PITCH + (uint32_t)(lane & 3) * 4;

    // ---- prologue: B stages 0,1 in flight; mask groups 0,1 in regs; prefetch ahead ----
    issueB(0);
    issueB(1);
    prefetch_chunk(0);
    prefetch_chunk(1);
    prefetch_chunk(2);
    load_frags(0, rawv[0]);
    load_frags(1, rawv[1]);
    CP_WAIT1();          // B(0) complete, B(1) may be in flight
    __syncthreads();

    const int TOTAL_G = CHUNKS * 4;
    for (int c = 0; c < CHUNKS; ++c) {
        if (c + 3 < CHUNKS) prefetch_chunk(c + 3);
        const uint32_t stg = sb + (uint32_t)(c % 3) * STAGE_SZ;
#pragma unroll
        for (int ks = 0; ks < 4; ++ks) {
            const int g = c * 4 + ks;
            uint32_t af[4];
            af[0] = pack01(rawv[g & 1][0]);
            af[1] = pack01(rawv[g & 1][1]);
            af[2] = pack01(rawv[g & 1][2]);
            af[3] = pack01(rawv[g & 1][3]);
            msum = __dp4a(af[0], 0x01010101u, msum);
            msum = __dp4a(af[1], 0x01010101u, msum);
            msum = __dp4a(af[2], 0x01010101u, msum);
            msum = __dp4a(af[3], 0x01010101u, msum);
            if (g + 2 < TOTAL_G) load_frags(g + 2, rawv[g & 1]);
            const uint32_t bk = stg + bOff + (uint32_t)ks * 32;
#pragma unroll
            for (int nj = 0; nj < 16; ++nj) {
                uint32_t b0, b1;
                const uint32_t ba = bk + (uint32_t)(nj * 8) * PITCH;
                asm volatile("ld.shared.b32 %0, [%1];" : "=r"(b0) : "r"(ba));
                asm volatile("ld.shared.b32 %0, [%1];" : "=r"(b1) : "r"(ba + 16));
                mma_s8(acc[nj], af, b0, b1);
            }
        }
        if (c + 2 < CHUNKS) issueB(c + 2);
        CP_WAIT1();       // B(c+1) complete; B(c+2) may remain in flight
        __syncthreads();  // stage c%3 fully consumed before its reuse at c+3
    }

    // ---- n_pairs reduce ----
#pragma unroll
    for (int o = 16; o; o >>= 1) msum += __shfl_down_sync(0xFFFFFFFFu, msum, o);
    if (lane == 0) atomicAdd(&g_npairs, msum);

    // ---- stage ca/sa [64 b][128 i-tile] f32 into smem (reuses B ring space) ----
    float* cas = reinterpret_cast<float*>(smem_raw);
    float* sas = cas + 64 * CA_PITCH;
    float* real_s = reinterpret_cast<float*>(smem_raw + ACC_OFF);
    float* imag_s = real_s + 64;
    if (tid < 64) { real_s[tid] = 0.0f; imag_s[tid] = 0.0f; }
    __syncthreads();   // ring reads done before overwrite
#pragma unroll
    for (int it = 0; it < 8; ++it) {
        const int idx = tid + it * 256;   // 0..2047 float4 tasks
        const int r = idx >> 5;
        const int q = idx & 31;
        *reinterpret_cast<float4*>(&cas[r * CA_PITCH + q * 4]) =
            *reinterpret_cast<const float4*>(&g_caf[(size_t)r * NA + i0 + q * 4]);
        *reinterpret_cast<float4*>(&sas[r * CA_PITCH + q * 4]) =
            *reinterpret_cast<const float4*>(&g_saf[(size_t)r * NA + i0 + q * 4]);
    }
    __syncthreads();

    // ---- epilogue: real_b += ca*Xc + sa*Xs ; imag_b += sa*Xc - ca*Xs ----
    {
        const float inv127 = 1.0f / 127.0f;
        const int tc  = (lane & 3) * 2;
        const int il0 = wid * 16 + (lane >> 2);
#pragma unroll
        for (int nj = 0; nj < 8; ++nj) {
#pragma unroll
            for (int h2 = 0; h2 < 2; ++h2) {
                const int b = nj * 8 + tc + h2;
                float rsum = 0.0f, isum = 0.0f;
#pragma unroll
                for (int hr = 0; hr < 2; ++hr) {
                    const int il = il0 + hr * 8;
                    const float Xc = __int2float_rn(acc[nj][hr * 2 + h2]);
                    const float Xs = __int2float_rn(acc[nj + 8][hr * 2 + h2]);
                    const float ca = cas[b * CA_PITCH + il];
                    const float sa = sas[b * CA_PITCH + il];
                    rsum = fmaf(ca, Xc, fmaf(sa, Xs, rsum));
                    isum = fmaf(sa, Xc, fmaf(-ca, Xs, isum));
                }
                atomicAdd(&real_s[b], rsum * inv127);
                atomicAdd(&imag_s[b], isum * inv127);
            }
        }
    }
    __syncthreads();
    if (tid < 64) {
        atomicAdd(&g_real[tid], real_s[tid]);
        atomicAdd(&g_imag[tid], imag_s[tid]);
    }
}

// ---------------- final ----------------
__global__ void plv_final(float* __restrict__ out) {
    const int b = threadIdx.x;
    if (b < BATCH) {
        const float np = fmaxf((float)g_npairs, 1.0f);
        const float r = g_real[b], i = g_imag[b];
        out[b] = sqrtf(r * r + i * i) / np;
    }
}

// ---------------- launch ----------------
extern "C" void kernel_launch(void* const* d_in, const int* in_sizes, int n_in,
                              void* d_out, int out_size) {
    (void)in_sizes; (void)n_in; (void)out_size;
    const float* pa = (const float*)d_in[0];
    const float* pb = (const float*)d_in[1];
    const int* mask = (const int*)d_in[2];
    float* out      = (float*)d_out;

    cudaFuncSetAttribute(plv_main, cudaFuncAttributeMaxDynamicSharedMemorySize, SMEM_BYTES);

    plv_prep<<<(BATCH * NA + 255) / 256, 256>>>(pa, pb);
    plv_main<<<dim3(NA / 128, JSPLIT), NTHREADS, SMEM_BYTES>>>(mask);
    plv_final<<<1, 64>>>(out);
}

// round 9
// speedup vs baseline: 1.7487x; 1.2681x over previous
#include <cuda_runtime.h>
#include <cuda_fp16.h>
#include <cstdint>
#include <math.h>

// ---------------- problem constants ----------------
static constexpr int BATCH  = 64;
static constexpr int NA     = 8192;     // i dimension (mask rows)
static constexpr int NB     = 8192;     // j dimension (mask cols)
static constexpr int TILE_K = 128;      // j per chunk
static constexpr int JSPLIT = 2;        // 64 i-tiles x 2 j-strips = 128 CTAs
static constexpr int CHUNKS = NB / TILE_K / JSPLIT;   // 32
static constexpr int NTHREADS = 256;

// smem: B ring (3 stages, fp16 [k=128][n=128], pitch 272B), later ca/sa f32
static constexpr int PITCH_B  = 272;                   // 17 x 16B
static constexpr int STAGE_SZ = 128 * PITCH_B;         // 34816 (x3 = 104448)
static constexpr int CA_PITCH = 132;                   // floats
static constexpr int ACC_OFF  = 3 * STAGE_SZ;          // 104448 (> 2*64*132*4)
static constexpr int SMEM_BYTES = ACC_OFF + 512;       // 104960

// ---------------- device scratch ----------------
__device__ __half g_B16[NB * 128];     // row j: [cb(b=0..63) | sb(b=0..63)] fp16
__device__ float  g_caf[BATCH * NA];   // cos(a), b-major
__device__ float  g_saf[BATCH * NA];   // sin(a)
__device__ float  g_real[BATCH];
__device__ float  g_imag[BATCH];
__device__ unsigned int g_npairs;

// ---------------- helpers ----------------
__device__ __forceinline__ uint32_t smem_u32(const void* p) {
    uint32_t a;
    asm("{ .reg .u64 t; cvta.to.shared.u64 t, %1; cvt.u32.u64 %0, t; }" : "=r"(a) : "l"(p));
    return a;
}
__device__ __forceinline__ void cp_async16(uint32_t s, const void* g) {
    asm volatile("cp.async.cg.shared.global [%0], [%1], 16;" :: "r"(s), "l"(g) : "memory");
}
#define CP_COMMIT()  asm volatile("cp.async.commit_group;" ::: "memory")
#define CP_WAIT1()   asm volatile("cp.async.wait_group 1;" ::: "memory")

__device__ __forceinline__ void prefetchL2(const void* g) {
    asm volatile("prefetch.global.L2 [%0];" :: "l"(g));
}

#define LDSM_X4_T(r, addr) \
    asm volatile("ldmatrix.sync.aligned.m8n8.x4.trans.shared.b16 {%0,%1,%2,%3}, [%4];" \
        : "=r"((r)[0]), "=r"((r)[1]), "=r"((r)[2]), "=r"((r)[3]) : "r"(addr))

__device__ __forceinline__ void mma_16816(float* d, const uint32_t* a, uint32_t b0, uint32_t b1) {
    asm volatile(
        "mma.sync.aligned.m16n8k16.row.col.f32.f16.f16.f32 "
        "{%0,%1,%2,%3}, {%4,%5,%6,%7}, {%8,%9}, {%0,%1,%2,%3};"
        : "+f"(d[0]), "+f"(d[1]), "+f"(d[2]), "+f"(d[3])
        : "r"(a[0]), "r"(a[1]), "r"(a[2]), "r"(a[3]), "r"(b0), "r"(b1));
}
// two mask ints {0,1} -> packed half2 {1.0h or 0.0h} (exact)
__device__ __forceinline__ uint32_t pack2h(const int2 v) {
    return (uint32_t)v.x * 0x3C00u + (uint32_t)v.y * 0x3C000000u;
}

// ---------------- prep: f32 cos/sin(a); fp16 trig table for B ----------------
__global__ void plv_prep(const float* __restrict__ pa, const float* __restrict__ pb) {
    int idx = blockIdx.x * blockDim.x + threadIdx.x;
    if (idx < BATCH * NA) {
        float s, c;
        sincosf(pa[idx], &s, &c);
        g_caf[idx] = c;
        g_saf[idx] = s;
        // B table: b = idx&63, j = idx>>6 -> coalesced writes to g_B16
        const int b = idx & 63;
        const int j = idx >> 6;
        sincosf(pb[(size_t)b * NB + j], &s, &c);
        g_B16[(size_t)j * 128 + b]      = __float2half_rn(c);
        g_B16[(size_t)j * 128 + 64 + b] = __float2half_rn(s);
    }
    if (blockIdx.x == 0) {
        if (threadIdx.x < BATCH) { g_real[threadIdx.x] = 0.0f; g_imag[threadIdx.x] = 0.0f; }
        if (threadIdx.x == BATCH) g_npairs = 0u;
    }
}

// ---------------- main: X = M @ Btrig fused with f32 ca/sa epilogue ----------------
__global__ void __launch_bounds__(NTHREADS, 1) plv_main(const int* __restrict__ mask) {
    extern __shared__ char smem_raw[];
    const uint32_t sb = smem_u32(smem_raw);

    const int tid  = threadIdx.x;
    const int wid  = tid >> 5;          // 8 warps: 16 i-rows each
    const int lane = tid & 31;
    const int i0   = blockIdx.x * 128;
    const int jb   = blockIdx.y * (NB / JSPLIT);

    // ---- B ring issue: g_B16 rows j0..j0+127 -> stage (chunk % 3) ----
    auto issueB = [&](int chunk) {
        const int j0 = jb + chunk * TILE_K;
        const uint32_t dst = sb + (uint32_t)(chunk % 3) * STAGE_SZ;
#pragma unroll
        for (int it = 0; it < 8; ++it) {
            const int idx = tid + it * 256;   // 2048 tasks: 128 rows x 16 x 16B
            const int k = idx >> 4;
            const int g = idx & 15;
            cp_async16(dst + (uint32_t)k * PITCH_B + (uint32_t)g * 16,
                       (const char*)g_B16 + ((size_t)(j0 + k) * 128 + (size_t)g * 8) * 2);
        }
        CP_COMMIT();
    };

    // ---- A fragments straight from mask gmem ----
    const int  tc   = (lane & 3) * 2;
    const int  arow = i0 + wid * 16 + (lane >> 2);
    const int* rp0  = mask + (size_t)arow * NB;
    const int* rp1  = rp0 + (size_t)8 * NB;

    // per k16-block: 4 x int2 (row, row+8) x (k: tc, tc+8)
    int2 rawv[2][4];
    auto load_kb = [&](int g, int2* r) {   // g = global k-block index (8 per chunk)
        const int j = jb + g * 16 + tc;
        r[0] = __ldcs((const int2*)(rp0 + j));
        r[1] = __ldcs((const int2*)(rp1 + j));
        r[2] = __ldcs((const int2*)(rp0 + j + 8));
        r[3] = __ldcs((const int2*)(rp1 + j + 8));
    };

    // L2 prefetch of one chunk's mask rows (lane&3==0 lanes cover all 16 rows)
    auto prefetch_chunk = [&](int chunk) {
        if ((lane & 3) == 0) {
            const int jc = jb + chunk * TILE_K;
#pragma unroll
            for (int g = 0; g < 4; ++g) {
                const int j = jc + g * 32;
                prefetchL2(rp0 + j);
                prefetchL2(rp1 + j);
            }
        }
    };

    float acc[16][4];
#pragma unroll
    for (int nj = 0; nj < 16; ++nj)
#pragma unroll
        for (int r = 0; r < 4; ++r) acc[nj][r] = 0.0f;

    unsigned int msum = 0;
    const uint32_t bOff = (uint32_t)(lane & 15) * PITCH_B + (uint32_t)(lane >> 4) * 16;

    // ---- prologue ----
    issueB(0);
    issueB(1);
    prefetch_chunk(0);
    prefetch_chunk(1);
    prefetch_chunk(2);
    load_kb(0, rawv[0]);
    load_kb(1, rawv[1]);
    CP_WAIT1();          // B(0) complete
    __syncthreads();

    const int TOTAL_G = CHUNKS * 8;
    for (int c = 0; c < CHUNKS; ++c) {
        if (c + 3 < CHUNKS) prefetch_chunk(c + 3);
        const uint32_t stg = sb + (uint32_t)(c % 3) * STAGE_SZ;
#pragma unroll
        for (int kb = 0; kb < 8; ++kb) {
            const int g = c * 8 + kb;
            uint32_t af[4];
            af[0] = pack2h(rawv[g & 1][0]);
            af[1] = pack2h(rawv[g & 1][1]);
            af[2] = pack2h(rawv[g & 1][2]);
            af[3] = pack2h(rawv[g & 1][3]);
            msum += (unsigned)(rawv[g & 1][0].x + rawv[g & 1][0].y
                             + rawv[g & 1][1].x + rawv[g & 1][1].y
                             + rawv[g & 1][2].x + rawv[g & 1][2].y
                             + rawv[g & 1][3].x + rawv[g & 1][3].y);
            if (g + 2 < TOTAL_G) load_kb(g + 2, rawv[g & 1]);
            const uint32_t bk = stg + bOff + (uint32_t)(kb * 16) * PITCH_B;
#pragma unroll
            for (int nj = 0; nj < 8; ++nj) {
                uint32_t bfr[4];
                LDSM_X4_T(bfr, bk + (uint32_t)nj * 32);
                mma_16816(acc[nj * 2 + 0], af, bfr[0], bfr[1]);
                mma_16816(acc[nj * 2 + 1], af, bfr[2], bfr[3]);
            }
        }
        if (c + 2 < CHUNKS) issueB(c + 2);
        CP_WAIT1();       // B(c+1) complete; B(c+2) may remain in flight
        __syncthreads();
    }

    // ---- n_pairs reduce ----
#pragma unroll
    for (int o = 16; o; o >>= 1) msum += __shfl_down_sync(0xFFFFFFFFu, msum, o);
    if (lane == 0) atomicAdd(&g_npairs, msum);

    // ---- stage ca/sa [64 b][128 i-tile] f32 into smem (reuses B ring space) ----
    float* cas = reinterpret_cast<float*>(smem_raw);
    float* sas = cas + 64 * CA_PITCH;
    float* real_s = reinterpret_cast<float*>(smem_raw + ACC_OFF);
    float* imag_s = real_s + 64;
    if (tid < 64) { real_s[tid] = 0.0f; imag_s[tid] = 0.0f; }
    __syncthreads();   // ring reads done before overwrite
#pragma unroll
    for (int it = 0; it < 8; ++it) {
        const int idx = tid + it * 256;   // 2048 float4 tasks
        const int r = idx >> 5;
        const int q = idx & 31;
        *reinterpret_cast<float4*>(&cas[r * CA_PITCH + q * 4]) =
            *reinterpret_cast<const float4*>(&g_caf[(size_t)r * NA + i0 + q * 4]);
        *reinterpret_cast<float4*>(&sas[r * CA_PITCH + q * 4]) =
            *reinterpret_cast<const float4*>(&g_saf[(size_t)r * NA + i0 + q * 4]);
    }
    __syncthreads();

    // ---- epilogue: real_b += ca*Xc + sa*Xs ; imag_b += sa*Xc - ca*Xs ----
    {
        const int il0 = wid * 16 + (lane >> 2);
#pragma unroll
        for (int nb8 = 0; nb8 < 8; ++nb8) {
#pragma unroll
            for (int h2 = 0; h2 < 2; ++h2) {
                const int b = nb8 * 8 + tc + h2;
                float rsum = 0.0f, isum = 0.0f;
#pragma unroll
                for (int hr = 0; hr < 2; ++hr) {
                    const int il = il0 + hr * 8;
                    const float Xc = acc[nb8 * 2 + h2][hr * 2 + 0] * 0.0f  // placeholder removed below
                                   + acc[nb8 * 2 + h2][hr * 2 + 0];
                    // NOTE: fragment reg mapping: r = hr*2 + (col&1); col parity handled by h2
                    (void)Xc;
                    const float xc = acc[nb8 * 2 + h2][hr * 2 + 0];
                    (void)xc;
                    const float Xcv = acc[nb8 * 2 + 0 + 0][0];
                    (void)Xcv;
                    const float xcc = 0.0f; (void)xcc;
                    const float ca = cas[b * CA_PITCH + il];
                    const float sa = sas[b * CA_PITCH + il];
                    // correct mapping: within n8 block nb8, thread cols are tc,tc+1 (h2 picks),
                    // regs: [hr*2 + h2] of acc[nb8] (cos, n<64) / acc[nb8+8] (sin)
                    const float XC = acc[nb8][hr * 2 + h2];
                    const float XS = acc[nb8 + 8][hr * 2 + h2];
                    rsum = fmaf(ca, XC, fmaf(sa, XS, rsum));
                    isum = fmaf(sa, XC, fmaf(-ca, XS, isum));
                }
                atomicAdd(&real_s[b], rsum);
                atomicAdd(&imag_s[b], isum);
            }
        }
    }
    __syncthreads();
    if (tid < 64) {
        atomicAdd(&g_real[tid], real_s[tid]);
        atomicAdd(&g_imag[tid], imag_s[tid]);
    }
}

// ---------------- final ----------------
__global__ void plv_final(float* __restrict__ out) {
    const int b = threadIdx.x;
    if (b < BATCH) {
        const float np = fmaxf((float)g_npairs, 1.0f);
        const float r = g_real[b], i = g_imag[b];
        out[b] = sqrtf(r * r + i * i) / np;
    }
}

// ---------------- launch ----------------
extern "C" void kernel_launch(void* const* d_in, const int* in_sizes, int n_in,
                              void* d_out, int out_size) {
    (void)in_sizes; (void)n_in; (void)out_size;
    const float* pa = (const float*)d_in[0];
    const float* pb = (const float*)d_in[1];
    const int* mask = (const int*)d_in[2];
    float* out      = (float*)d_out;

    cudaFuncSetAttribute(plv_main, cudaFuncAttributeMaxDynamicSharedMemorySize, SMEM_BYTES);

    plv_prep<<<(BATCH * NA + 255) / 256, 256>>>(pa, pb);
    plv_main<<<dim3(NA / 128, JSPLIT), NTHREADS, SMEM_BYTES>>>(mask);
    plv_final<<<1, 64>>>(out);
}

// round 10
// speedup vs baseline: 2.1297x; 1.2178x over previous
#include <cuda_runtime.h>
#include <cuda_fp16.h>
#include <cstdint>
#include <math.h>

// ---------------- problem constants ----------------
static constexpr int BATCH  = 64;
static constexpr int NA     = 8192;     // i dimension (mask rows)
static constexpr int NB     = 8192;     // j dimension (mask cols)
static constexpr int TILE_K = 128;      // j per chunk
static constexpr int JSPLIT = 2;        // 64 i-tiles x 2 j-strips = 128 CTAs
static constexpr int CHUNKS = NB / TILE_K / JSPLIT;   // 32
static constexpr int NTHREADS = 256;

// smem layout
static constexpr int RAW_PITCH = 544;                  // 512B data + 32B pad (8-bank row shift)
static constexpr int RAW_STAGE = 128 * RAW_PITCH;      // 69632
static constexpr int B_BASE    = 2 * RAW_STAGE;        // 139264
static constexpr int PITCH_B   = 272;                  // fp16 B tile pitch (17 x 16B)
static constexpr int B_STAGE   = 128 * PITCH_B;        // 34816
static constexpr int ACC_OFF   = B_BASE + 2 * B_STAGE; // 208896
static constexpr int SMEM_BYTES = ACC_OFF + 512;       // 209408
static constexpr int CA_PITCH  = 132;                  // floats

// ---------------- device scratch ----------------
__device__ __half g_B16[NB * 128];     // row j: [cb(b=0..63) | sb(b=0..63)] fp16
__device__ float  g_caf[BATCH * NA];   // cos(a), b-major
__device__ float  g_saf[BATCH * NA];   // sin(a)
__device__ float  g_real[BATCH];
__device__ float  g_imag[BATCH];
__device__ unsigned int g_npairs;

// ---------------- helpers ----------------
__device__ __forceinline__ uint32_t smem_u32(const void* p) {
    uint32_t a;
    asm("{ .reg .u64 t; cvta.to.shared.u64 t, %1; cvt.u32.u64 %0, t; }" : "=r"(a) : "l"(p));
    return a;
}
__device__ __forceinline__ void cp_async16(uint32_t s, const void* g) {
    asm volatile("cp.async.cg.shared.global [%0], [%1], 16;" :: "r"(s), "l"(g) : "memory");
}
#define CP_COMMIT()  asm volatile("cp.async.commit_group;" ::: "memory")
#define CP_WAIT1()   asm volatile("cp.async.wait_group 1;" ::: "memory")
#define CP_WAIT0()   asm volatile("cp.async.wait_group 0;" ::: "memory")

__device__ __forceinline__ void lds64(int2& v, uint32_t a) {
    asm volatile("ld.shared.v2.u32 {%0,%1}, [%2];" : "=r"(v.x), "=r"(v.y) : "r"(a));
}

#define LDSM_X4_T(r, addr) \
    asm volatile("ldmatrix.sync.aligned.m8n8.x4.trans.shared.b16 {%0,%1,%2,%3}, [%4];" \
        : "=r"((r)[0]), "=r"((r)[1]), "=r"((r)[2]), "=r"((r)[3]) : "r"(addr))

__device__ __forceinline__ void mma_16816(float* d, const uint32_t* a, uint32_t b0, uint32_t b1) {
    asm volatile(
        "mma.sync.aligned.m16n8k16.row.col.f32.f16.f16.f32 "
        "{%0,%1,%2,%3}, {%4,%5,%6,%7}, {%8,%9}, {%0,%1,%2,%3};"
        : "+f"(d[0]), "+f"(d[1]), "+f"(d[2]), "+f"(d[3])
        : "r"(a[0]), "r"(a[1]), "r"(a[2]), "r"(a[3]), "r"(b0), "r"(b1));
}
// two mask ints {0,1} -> packed half2 {1.0h | 0.0h} (exact)
__device__ __forceinline__ uint32_t pack2h(const int2 v) {
    return (uint32_t)v.x * 0x3C00u + (uint32_t)v.y * 0x3C000000u;
}

// ---------------- prep: f32 cos/sin(a); fp16 trig table for B ----------------
__global__ void plv_prep(const float* __restrict__ pa, const float* __restrict__ pb) {
    int idx = blockIdx.x * blockDim.x + threadIdx.x;
    if (idx < BATCH * NA) {
        const int b = idx >> 13;
        const int j = idx & (NA - 1);
        float s, c;
        sincosf(pa[idx], &s, &c);
        g_caf[idx] = c;
        g_saf[idx] = s;
        sincosf(pb[idx], &s, &c);               // coalesced read; scattered 2B writes (L2-merged)
        g_B16[(size_t)j * 128 + b]      = __float2half_rn(c);
        g_B16[(size_t)j * 128 + 64 + b] = __float2half_rn(s);
    }
    if (blockIdx.x == 0) {
        if (threadIdx.x < BATCH) { g_real[threadIdx.x] = 0.0f; g_imag[threadIdx.x] = 0.0f; }
        if (threadIdx.x == BATCH) g_npairs = 0u;
    }
}

// ---------------- main: X = M @ Btrig, both operands smem-staged ----------------
__global__ void __launch_bounds__(NTHREADS, 1) plv_main(const int* __restrict__ mask) {
    extern __shared__ char smem_raw[];
    const uint32_t sb = smem_u32(smem_raw);

    const int tid  = threadIdx.x;
    const int wid  = tid >> 5;
    const int lane = tid & 31;
    const int wm   = wid >> 1;          // 0..3: 32 i-rows each
    const int wn   = wid & 1;           // 0..1: 64 batch-cols each
    const int i0   = blockIdx.x * 128;
    const int jb   = blockIdx.y * (NB / JSPLIT);

    // ---- issue chunk c: raw mask (64KB) + B trig (32KB) as ONE commit group ----
    auto issue = [&](int chunk) {
        const int s  = chunk & 1;
        const int j0 = jb + chunk * TILE_K;
        // raw mask [k=row i][n=j]: 4096 16B tasks
        const uint32_t rdst = sb + (uint32_t)s * RAW_STAGE;
        const int* src = mask + (size_t)i0 * NB + j0;
#pragma unroll
        for (int it = 0; it < 16; ++it) {
            const int idx = tid + it * 256;
            const int k = idx >> 5;
            const int g = idx & 31;
            cp_async16(rdst + (uint32_t)k * RAW_PITCH + (uint32_t)g * 16,
                       src + (size_t)k * NB + g * 4);
        }
        // B trig rows j0..j0+127: 2048 16B tasks
        const uint32_t bdst = sb + B_BASE + (uint32_t)s * B_STAGE;
#pragma unroll
        for (int it = 0; it < 8; ++it) {
            const int idx = tid + it * 256;
            const int k = idx >> 4;
            const int g = idx & 15;
            cp_async16(bdst + (uint32_t)k * PITCH_B + (uint32_t)g * 16,
                       (const char*)g_B16 + ((size_t)(j0 + k) * 128 + (size_t)g * 8) * 2);
        }
        CP_COMMIT();
    };

    float acc[2][8][4];
#pragma unroll
    for (int i = 0; i < 2; ++i)
#pragma unroll
        for (int j = 0; j < 8; ++j)
#pragma unroll
            for (int r = 0; r < 4; ++r) acc[i][j][r] = 0.0f;

    unsigned int msum = 0;
    const int tc = (lane & 3) * 2;      // j pair base within k16 block

    auto compute = [&](int s) {
        const uint32_t rawS = sb + (uint32_t)s * RAW_STAGE;
        const uint32_t stgB = sb + B_BASE + (uint32_t)s * B_STAGE;
        const uint32_t aBase = rawS + (uint32_t)(wm * 32 + (lane >> 2)) * RAW_PITCH
                             + (uint32_t)(lane & 3) * 8;
        const uint32_t bBase = stgB + (uint32_t)(wn * 64) * 2
                             + (uint32_t)(lane & 15) * PITCH_B + (uint32_t)(lane >> 4) * 16;
#pragma unroll
        for (int kb = 0; kb < 8; ++kb) {
            const uint32_t ak = aBase + (uint32_t)kb * 64;
            int2 r0, r1, r2, r3, r4, r5, r6, r7;
            lds64(r0, ak);
            lds64(r1, ak + 8u * RAW_PITCH);
            lds64(r2, ak + 32u);
            lds64(r3, ak + 8u * RAW_PITCH + 32u);
            lds64(r4, ak + 16u * RAW_PITCH);
            lds64(r5, ak + 24u * RAW_PITCH);
            lds64(r6, ak + 16u * RAW_PITCH + 32u);
            lds64(r7, ak + 24u * RAW_PITCH + 32u);
            uint32_t af0[4] = {pack2h(r0), pack2h(r1), pack2h(r2), pack2h(r3)};
            uint32_t af1[4] = {pack2h(r4), pack2h(r5), pack2h(r6), pack2h(r7)};
            if (wn == 0) {
                msum += (unsigned)(r0.x + r0.y + r1.x + r1.y + r2.x + r2.y + r3.x + r3.y
                                 + r4.x + r4.y + r5.x + r5.y + r6.x + r6.y + r7.x + r7.y);
            }
            const uint32_t bk = bBase + (uint32_t)(kb * 16) * PITCH_B;
#pragma unroll
            for (int nj = 0; nj < 4; ++nj) {
                uint32_t bfr[4];
                LDSM_X4_T(bfr, bk + (uint32_t)nj * 32);
                mma_16816(acc[0][nj * 2 + 0], af0, bfr[0], bfr[1]);
                mma_16816(acc[0][nj * 2 + 1], af0, bfr[2], bfr[3]);
                mma_16816(acc[1][nj * 2 + 0], af1, bfr[0], bfr[1]);
                mma_16816(acc[1][nj * 2 + 1], af1, bfr[2], bfr[3]);
            }
        }
    };

    // ---------------- pipeline: 2-stage double buffer ----------------
    issue(0);
    issue(1);
    CP_WAIT1();          // group(0) complete
    __syncthreads();

    for (int c = 0; c < CHUNKS; ++c) {
        compute(c & 1);
        __syncthreads();                 // all warps done reading stage c&1
        if (c + 2 < CHUNKS) {
            issue(c + 2);                // overwrites stage c&1
            CP_WAIT1();                  // group(c+1) complete
        } else {
            CP_WAIT0();                  // tail: ensure last group complete
        }
        __syncthreads();
    }

    // ---- n_pairs reduce (wn==0 warps counted each element once) ----
#pragma unroll
    for (int o = 16; o; o >>= 1) msum += __shfl_down_sync(0xFFFFFFFFu, msum, o);
    if (wn == 0 && lane == 0) atomicAdd(&g_npairs, msum);

    // ---- stage ca/sa [64 b][128 i-tile] f32 into smem (reuses raw ring space) ----
    float* cas = reinterpret_cast<float*>(smem_raw);
    float* sas = cas + 64 * CA_PITCH;
    float* real_s = reinterpret_cast<float*>(smem_raw + ACC_OFF);
    float* imag_s = real_s + 64;
    if (tid < 64) { real_s[tid] = 0.0f; imag_s[tid] = 0.0f; }
    __syncthreads();
#pragma unroll
    for (int it = 0; it < 8; ++it) {
        const int idx = tid + it * 256;   // 2048 float4 tasks
        const int r = idx >> 5;
        const int q = idx & 31;
        *reinterpret_cast<float4*>(&cas[r * CA_PITCH + q * 4]) =
            *reinterpret_cast<const float4*>(&g_caf[(size_t)r * NA + i0 + q * 4]);
        *reinterpret_cast<float4*>(&sas[r * CA_PITCH + q * 4]) =
            *reinterpret_cast<const float4*>(&g_saf[(size_t)r * NA + i0 + q * 4]);
    }
    __syncthreads();

    // ---- epilogue (separable): wn=0 holds Xc -> += ca*Xc / sa*Xc ;
    //                            wn=1 holds Xs -> += sa*Xs / -ca*Xs ----
    {
        const int il0 = wm * 32 + (lane >> 2);
#pragma unroll
        for (int nj2 = 0; nj2 < 8; ++nj2) {
#pragma unroll
            for (int h2 = 0; h2 < 2; ++h2) {
                const int b = nj2 * 8 + tc + h2;
                float rsum = 0.0f, isum = 0.0f;
#pragma unroll
                for (int mi = 0; mi < 2; ++mi) {
#pragma unroll
                    for (int hr = 0; hr < 2; ++hr) {
                        const int il = il0 + mi * 16 + hr * 8;
                        const float X  = acc[mi][nj2][hr * 2 + h2];
                        const float ca = cas[b * CA_PITCH + il];
                        const float sa = sas[b * CA_PITCH + il];
                        if (wn == 0) { rsum = fmaf(ca, X, rsum); isum = fmaf(sa, X, isum); }
                        else         { rsum = fmaf(sa, X, rsum); isum = fmaf(-ca, X, isum); }
                    }
                }
                atomicAdd(&real_s[b], rsum);
                atomicAdd(&imag_s[b], isum);
            }
        }
    }
    __syncthreads();
    if (tid < 64) {
        atomicAdd(&g_real[tid], real_s[tid]);
        atomicAdd(&g_imag[tid], imag_s[tid]);
    }
}

// ---------------- final ----------------
__global__ void plv_final(float* __restrict__ out) {
    const int b = threadIdx.x;
    if (b < BATCH) {
        const float np = fmaxf((float)g_npairs, 1.0f);
        const float r = g_real[b], i = g_imag[b];
        out[b] = sqrtf(r * r + i * i) / np;
    }
}

// ---------------- launch ----------------
extern "C" void kernel_launch(void* const* d_in, const int* in_sizes, int n_in,
                              void* d_out, int out_size) {
    (void)in_sizes; (void)n_in; (void)out_size;
    const float* pa = (const float*)d_in[0];
    const float* pb = (const float*)d_in[1];
    const int* mask = (const int*)d_in[2];
    float* out      = (float*)d_out;

    cudaFuncSetAttribute(plv_main, cudaFuncAttributeMaxDynamicSharedMemorySize, SMEM_BYTES);

    plv_prep<<<(BATCH * NA + 255) / 256, 256>>>(pa, pb);
    plv_main<<<dim3(NA / 128, JSPLIT), NTHREADS, SMEM_BYTES>>>(mask);
    plv_final<<<1, 64>>>(out);
}